// round 2
// baseline (speedup 1.0000x reference)
#include <cuda_runtime.h>
#include <math.h>

#define Bsz 2
#define Seq 2048
#define Din 1024
#define Dout 1024
#define NH 16
#define HD 64
#define Mrows (Bsz * Seq)  // 4096

// Scratch: Q/K/V in head-split layout [B][H][S][HD], ctx in [B*S][Dout]
__device__ float g_q[(size_t)Bsz * NH * Seq * HD];
__device__ float g_k[(size_t)Bsz * NH * Seq * HD];
__device__ float g_v[(size_t)Bsz * NH * Seq * HD];
__device__ float g_ctx[(size_t)Mrows * Dout];

// ---------------------------------------------------------------------------
// GEMM tiling: 128x64 block tile, K-tile 16, 256 threads, 8x4 per thread
// ---------------------------------------------------------------------------
#define GBM 128
#define GBN 64
#define GBK 16

__global__ __launch_bounds__(256) void qkv_gemm_kernel(
    const float* __restrict__ x,
    const float* __restrict__ Wq,
    const float* __restrict__ Wk,
    const float* __restrict__ Wv)
{
    const float* W = (blockIdx.z == 0) ? Wq : (blockIdx.z == 1 ? Wk : Wv);
    float* out = (blockIdx.z == 0) ? g_q : (blockIdx.z == 1 ? g_k : g_v);

    __shared__ __align__(16) float As[GBK][GBM + 4];  // transposed A tile
    __shared__ __align__(16) float Bs[GBK][GBN];

    const int tid = threadIdx.x;
    const int tx = tid & 15;
    const int ty = tid >> 4;
    const int m0 = blockIdx.y * GBM;
    const int n0 = blockIdx.x * GBN;

    float acc[8][4];
#pragma unroll
    for (int i = 0; i < 8; i++)
#pragma unroll
        for (int j = 0; j < 4; j++) acc[i][j] = 0.f;

    for (int k0 = 0; k0 < Din; k0 += GBK) {
        // Load A tile (128x16) transposed into smem
#pragma unroll
        for (int i = 0; i < 2; i++) {
            int idx = tid + i * 256;
            int row = idx >> 2;
            int c4 = (idx & 3) << 2;
            float4 a = *(const float4*)&x[(size_t)(m0 + row) * Din + k0 + c4];
            As[c4 + 0][row] = a.x;
            As[c4 + 1][row] = a.y;
            As[c4 + 2][row] = a.z;
            As[c4 + 3][row] = a.w;
        }
        // Load B tile (16x64)
        {
            int row = tid >> 4;
            int c4 = (tid & 15) << 2;
            *(float4*)&Bs[row][c4] =
                *(const float4*)&W[(size_t)(k0 + row) * Dout + n0 + c4];
        }
        __syncthreads();

#pragma unroll
        for (int k = 0; k < GBK; k++) {
            float a[8], b[4];
            float4 a0 = *(const float4*)&As[k][ty * 8];
            float4 a1 = *(const float4*)&As[k][ty * 8 + 4];
            a[0] = a0.x; a[1] = a0.y; a[2] = a0.z; a[3] = a0.w;
            a[4] = a1.x; a[5] = a1.y; a[6] = a1.z; a[7] = a1.w;
            float4 b0 = *(const float4*)&Bs[k][tx * 4];
            b[0] = b0.x; b[1] = b0.y; b[2] = b0.z; b[3] = b0.w;
#pragma unroll
            for (int i = 0; i < 8; i++)
#pragma unroll
                for (int j = 0; j < 4; j++)
                    acc[i][j] = fmaf(a[i], b[j], acc[i][j]);
        }
        __syncthreads();
    }

    // Head-split store: one head per 64-wide N tile
    const int h = n0 >> 6;
#pragma unroll
    for (int i = 0; i < 8; i++) {
        int m = m0 + ty * 8 + i;
        int bb = m >> 11;           // m / Seq
        int s = m & (Seq - 1);      // m % Seq
#pragma unroll
        for (int j = 0; j < 4; j++) {
            int d = tx * 4 + j;
            out[(((size_t)bb * NH + h) * Seq + s) * HD + d] = acc[i][j];
        }
    }
}

__global__ __launch_bounds__(256) void out_gemm_kernel(
    const float* __restrict__ Wo,
    const float* __restrict__ bias,
    float* __restrict__ out)
{
    __shared__ __align__(16) float As[GBK][GBM + 4];
    __shared__ __align__(16) float Bs[GBK][GBN];

    const int tid = threadIdx.x;
    const int tx = tid & 15;
    const int ty = tid >> 4;
    const int m0 = blockIdx.y * GBM;
    const int n0 = blockIdx.x * GBN;

    float acc[8][4];
#pragma unroll
    for (int i = 0; i < 8; i++)
#pragma unroll
        for (int j = 0; j < 4; j++) acc[i][j] = 0.f;

    for (int k0 = 0; k0 < Dout; k0 += GBK) {
#pragma unroll
        for (int i = 0; i < 2; i++) {
            int idx = tid + i * 256;
            int row = idx >> 2;
            int c4 = (idx & 3) << 2;
            float4 a = *(const float4*)&g_ctx[(size_t)(m0 + row) * Dout + k0 + c4];
            As[c4 + 0][row] = a.x;
            As[c4 + 1][row] = a.y;
            As[c4 + 2][row] = a.z;
            As[c4 + 3][row] = a.w;
        }
        {
            int row = tid >> 4;
            int c4 = (tid & 15) << 2;
            *(float4*)&Bs[row][c4] =
                *(const float4*)&Wo[(size_t)(k0 + row) * Dout + n0 + c4];
        }
        __syncthreads();

#pragma unroll
        for (int k = 0; k < GBK; k++) {
            float a[8], b[4];
            float4 a0 = *(const float4*)&As[k][ty * 8];
            float4 a1 = *(const float4*)&As[k][ty * 8 + 4];
            a[0] = a0.x; a[1] = a0.y; a[2] = a0.z; a[3] = a0.w;
            a[4] = a1.x; a[5] = a1.y; a[6] = a1.z; a[7] = a1.w;
            float4 b0 = *(const float4*)&Bs[k][tx * 4];
            b[0] = b0.x; b[1] = b0.y; b[2] = b0.z; b[3] = b0.w;
#pragma unroll
            for (int i = 0; i < 8; i++)
#pragma unroll
                for (int j = 0; j < 4; j++)
                    acc[i][j] = fmaf(a[i], b[j], acc[i][j]);
        }
        __syncthreads();
    }

#pragma unroll
    for (int i = 0; i < 8; i++) {
        int m = m0 + ty * 8 + i;
#pragma unroll
        for (int j = 0; j < 4; j++) {
            int n = n0 + tx * 4 + j;
            out[(size_t)m * Dout + n] = acc[i][j] + bias[n];
        }
    }
}

// ---------------------------------------------------------------------------
// Flash-style causal attention: one CTA per (b, h, 64-row q-tile)
// 256 threads as 16x16; each thread owns a 4x4 microtile.
// Smem: Qs, Ks (aliased as P after scores), Vs — pitch 65 floats.
// ---------------------------------------------------------------------------
#define AP 65
#define ATT_SMEM (3 * 64 * AP * 4)

__global__ __launch_bounds__(256) void attn_kernel()
{
    extern __shared__ float sm[];
    float* Qs = sm;                 // 64 x AP
    float* Ks = Qs + 64 * AP;       // 64 x AP (reused for P)
    float* Vs = Ks + 64 * AP;       // 64 x AP

    const int tid = threadIdx.x;
    const int tx = tid & 15;
    const int ty = tid >> 4;
    const int qt = blockIdx.x;
    const int h = blockIdx.y;
    const int bb = blockIdx.z;
    const int q0 = qt * 64;
    const size_t base = ((size_t)bb * NH + h) * Seq * HD;

    // Load Q tile (64 x 64)
#pragma unroll
    for (int c = 0; c < 4; c++) {
        int idx = tid + c * 256;
        int row = idx >> 4;
        int c4 = (idx & 15) << 2;
        float4 qv = *(const float4*)&g_q[base + (size_t)(q0 + row) * HD + c4];
        Qs[row * AP + c4 + 0] = qv.x;
        Qs[row * AP + c4 + 1] = qv.y;
        Qs[row * AP + c4 + 2] = qv.z;
        Qs[row * AP + c4 + 3] = qv.w;
    }

    float acc[4][4];
#pragma unroll
    for (int i = 0; i < 4; i++)
#pragma unroll
        for (int j = 0; j < 4; j++) acc[i][j] = 0.f;
    float mrow[4], lrow[4];
#pragma unroll
    for (int i = 0; i < 4; i++) { mrow[i] = -1e30f; lrow[i] = 0.f; }

    for (int kt = 0; kt <= qt; kt++) {
        const int k0 = kt * 64;
        __syncthreads();  // prev PV reads done (and Q visible on first iter)

        // Load K and V tiles
#pragma unroll
        for (int c = 0; c < 4; c++) {
            int idx = tid + c * 256;
            int row = idx >> 4;
            int c4 = (idx & 15) << 2;
            float4 kv = *(const float4*)&g_k[base + (size_t)(k0 + row) * HD + c4];
            Ks[row * AP + c4 + 0] = kv.x;
            Ks[row * AP + c4 + 1] = kv.y;
            Ks[row * AP + c4 + 2] = kv.z;
            Ks[row * AP + c4 + 3] = kv.w;
            float4 vv = *(const float4*)&g_v[base + (size_t)(k0 + row) * HD + c4];
            Vs[row * AP + c4 + 0] = vv.x;
            Vs[row * AP + c4 + 1] = vv.y;
            Vs[row * AP + c4 + 2] = vv.z;
            Vs[row * AP + c4 + 3] = vv.w;
        }
        __syncthreads();

        // S = Q @ K^T  (4x4 per thread)
        float s[4][4];
#pragma unroll
        for (int i = 0; i < 4; i++)
#pragma unroll
            for (int j = 0; j < 4; j++) s[i][j] = 0.f;
#pragma unroll 4
        for (int d = 0; d < HD; d++) {
            float qv[4], kv[4];
#pragma unroll
            for (int i = 0; i < 4; i++) qv[i] = Qs[(ty * 4 + i) * AP + d];
#pragma unroll
            for (int j = 0; j < 4; j++) kv[j] = Ks[(tx * 4 + j) * AP + d];
#pragma unroll
            for (int i = 0; i < 4; i++)
#pragma unroll
                for (int j = 0; j < 4; j++)
                    s[i][j] = fmaf(qv[i], kv[j], s[i][j]);
        }

        // Scale + causal mask (only diagonal tile needs masking)
#pragma unroll
        for (int i = 0; i < 4; i++)
#pragma unroll
            for (int j = 0; j < 4; j++) {
                s[i][j] *= 0.125f;  // 1/sqrt(64)
                if (kt == qt && (tx * 4 + j) > (ty * 4 + i)) s[i][j] = -1e30f;
            }

        // Online softmax update (row reductions via shfl across tx lanes)
        float p[4][4];
#pragma unroll
        for (int i = 0; i < 4; i++) {
            float mx = fmaxf(fmaxf(s[i][0], s[i][1]), fmaxf(s[i][2], s[i][3]));
#pragma unroll
            for (int off = 8; off >= 1; off >>= 1)
                mx = fmaxf(mx, __shfl_xor_sync(0xffffffffu, mx, off));
            float mn = fmaxf(mrow[i], mx);
            float alpha = __expf(mrow[i] - mn);
            mrow[i] = mn;
            float rs = 0.f;
#pragma unroll
            for (int j = 0; j < 4; j++) {
                p[i][j] = __expf(s[i][j] - mn);
                rs += p[i][j];
            }
#pragma unroll
            for (int off = 8; off >= 1; off >>= 1)
                rs += __shfl_xor_sync(0xffffffffu, rs, off);
            lrow[i] = lrow[i] * alpha + rs;
#pragma unroll
            for (int j = 0; j < 4; j++) acc[i][j] *= alpha;
        }

        __syncthreads();  // all Ks reads done before overwriting with P
#pragma unroll
        for (int i = 0; i < 4; i++)
#pragma unroll
            for (int j = 0; j < 4; j++)
                Ks[(ty * 4 + i) * AP + tx * 4 + j] = p[i][j];
        __syncthreads();

        // acc += P @ V
#pragma unroll 4
        for (int c = 0; c < 64; c++) {
            float pv[4], vv[4];
#pragma unroll
            for (int i = 0; i < 4; i++) pv[i] = Ks[(ty * 4 + i) * AP + c];
#pragma unroll
            for (int j = 0; j < 4; j++) vv[j] = Vs[c * AP + tx * 4 + j];
#pragma unroll
            for (int i = 0; i < 4; i++)
#pragma unroll
                for (int j = 0; j < 4; j++)
                    acc[i][j] = fmaf(pv[i], vv[j], acc[i][j]);
        }
    }

    // Epilogue: ctx[b, s, h*HD + d] = acc / l
#pragma unroll
    for (int i = 0; i < 4; i++) {
        float inv = 1.f / lrow[i];
        int srow = q0 + ty * 4 + i;
#pragma unroll
        for (int j = 0; j < 4; j++) {
            g_ctx[((size_t)bb * Seq + srow) * Dout + h * HD + tx * 4 + j] =
                acc[i][j] * inv;
        }
    }
}

// ---------------------------------------------------------------------------
extern "C" void kernel_launch(void* const* d_in, const int* in_sizes, int n_in,
                              void* d_out, int out_size)
{
    const float* x  = (const float*)d_in[0];
    const float* Wq = (const float*)d_in[1];
    const float* Wk = (const float*)d_in[2];
    const float* Wv = (const float*)d_in[3];
    const float* Wo = (const float*)d_in[4];
    const float* bo = (const float*)d_in[5];
    float* out = (float*)d_out;

    cudaFuncSetAttribute(attn_kernel,
                         cudaFuncAttributeMaxDynamicSharedMemorySize, ATT_SMEM);

    qkv_gemm_kernel<<<dim3(Dout / GBN, Mrows / GBM, 3), 256>>>(x, Wq, Wk, Wv);
    attn_kernel<<<dim3(Seq / 64, NH, Bsz), 256, ATT_SMEM>>>();
    out_gemm_kernel<<<dim3(Dout / GBN, Mrows / GBM), 256>>>(Wo, bo, out);
}

// round 17
// speedup vs baseline: 1.6355x; 1.6355x over previous
#include <cuda_runtime.h>
#include <cuda_bf16.h>
#include <cstdint>
#include <math.h>

#define Bsz 2
#define Seq 2048
#define Din 1024
#define Dout 1024
#define NH 16
#define HD 64
#define Mrows (Bsz * Seq)  // 4096

// ---------------------------------------------------------------------------
// Scratch (device globals; no runtime allocation allowed)
// ---------------------------------------------------------------------------
__device__ __nv_bfloat16 g_wh[4 * (size_t)Din * Dout];  // weights hi, [k][n]
__device__ __nv_bfloat16 g_wl[4 * (size_t)Din * Dout];  // weights lo, [k][n]
__device__ float g_q[(size_t)Bsz * NH * Seq * HD];
__device__ float g_k[(size_t)Bsz * NH * Seq * HD];
__device__ float g_v[(size_t)Bsz * NH * Seq * HD];
__device__ float g_ctx[(size_t)Mrows * Dout];

// ---------------------------------------------------------------------------
// Warp-MMA helpers (baseline ISA: legal on compute_103 without 'a' feature)
// ---------------------------------------------------------------------------
__device__ __forceinline__ uint32_t smem_u32(const void* p) {
    uint32_t a;
    asm("{ .reg .u64 t; cvta.to.shared.u64 t, %1; cvt.u32.u64 %0, t; }"
        : "=r"(a) : "l"(p));
    return a;
}
__device__ __forceinline__ void mma16816(float* c, const uint32_t* a,
                                         const uint32_t* b) {
    asm volatile(
        "mma.sync.aligned.m16n8k16.row.col.f32.bf16.bf16.f32 "
        "{%0,%1,%2,%3}, {%4,%5,%6,%7}, {%8,%9}, {%0,%1,%2,%3};"
        : "+f"(c[0]), "+f"(c[1]), "+f"(c[2]), "+f"(c[3])
        : "r"(a[0]), "r"(a[1]), "r"(a[2]), "r"(a[3]), "r"(b[0]), "r"(b[1]));
}
__device__ __forceinline__ void ldsm_x4(uint32_t* r, uint32_t addr) {
    asm volatile("ldmatrix.sync.aligned.m8n8.x4.shared.b16 {%0,%1,%2,%3}, [%4];"
                 : "=r"(r[0]), "=r"(r[1]), "=r"(r[2]), "=r"(r[3]) : "r"(addr));
}
__device__ __forceinline__ void ldsm_x4_t(uint32_t* r, uint32_t addr) {
    asm volatile("ldmatrix.sync.aligned.m8n8.x4.trans.shared.b16 {%0,%1,%2,%3}, [%4];"
                 : "=r"(r[0]), "=r"(r[1]), "=r"(r[2]), "=r"(r[3]) : "r"(addr));
}
__device__ __forceinline__ uint32_t pack_bf2(__nv_bfloat16 a, __nv_bfloat16 b) {
    __nv_bfloat162 t(a, b);
    return *reinterpret_cast<uint32_t*>(&t);
}

// ---------------------------------------------------------------------------
// Weight convert: W[k][n] fp32 -> hi/lo bf16 (layout preserved)
// ---------------------------------------------------------------------------
__global__ __launch_bounds__(256) void wconv_kernel(const float* __restrict__ Wq,
                                                    const float* __restrict__ Wk,
                                                    const float* __restrict__ Wv,
                                                    const float* __restrict__ Wo) {
    const int w = blockIdx.y;
    const float* W = (w == 0) ? Wq : (w == 1) ? Wk : (w == 2) ? Wv : Wo;
    size_t i = (size_t)blockIdx.x * 256 + threadIdx.x;  // float4 index
    float4 v = ((const float4*)W)[i];
    __nv_bfloat16 h0 = __float2bfloat16(v.x), h1 = __float2bfloat16(v.y);
    __nv_bfloat16 h2 = __float2bfloat16(v.z), h3 = __float2bfloat16(v.w);
    __nv_bfloat16 l0 = __float2bfloat16(v.x - __bfloat162float(h0));
    __nv_bfloat16 l1 = __float2bfloat16(v.y - __bfloat162float(h1));
    __nv_bfloat16 l2 = __float2bfloat16(v.z - __bfloat162float(h2));
    __nv_bfloat16 l3 = __float2bfloat16(v.w - __bfloat162float(h3));
    uint2 hp = make_uint2(pack_bf2(h0, h1), pack_bf2(h2, h3));
    uint2 lp = make_uint2(pack_bf2(l0, l1), pack_bf2(l2, l3));
    ((uint2*)(g_wh + (size_t)w * Din * Dout))[i] = hp;
    ((uint2*)(g_wl + (size_t)w * Din * Dout))[i] = lp;
}

// ---------------------------------------------------------------------------
// bf16x3 mma.sync GEMM: C[128,128] per block = A(fp32)[M,K] * B(hi/lo)[K,N]
// 256 threads = 8 warps (4 along M x 2 along N); warp tile 32x64.
// ---------------------------------------------------------------------------
#define BM 128
#define BN 128
#define BK 32
#define ASTR 40    // A smem row pitch in bf16 (80B; ldmatrix banks 5r mod 8)
#define BSTR 136   // B smem row pitch in bf16 (272B; ldmatrix banks r mod 8)
#define A_STG (BM * ASTR * 2)   // 10240 B per stage per half
#define B_STG (BK * BSTR * 2)   // 8704 B per stage per half
#define OFF_AH 0
#define OFF_AL (2 * A_STG)            // 20480
#define OFF_BH (4 * A_STG)            // 40960
#define OFF_BL (OFF_BH + 2 * B_STG)   // 58368
#define GEMM_SMEM (OFF_BL + 2 * B_STG)  // 75776 B

__device__ __forceinline__ void gemm_mainloop(
    const float* __restrict__ A,          // block's A rows: A + m0*1024
    const __nv_bfloat16* __restrict__ Bh, // + n0
    const __nv_bfloat16* __restrict__ Bl, // + n0
    char* smc, float acc[2][8][4]) {
    const int tid = threadIdx.x;
    const int lane = tid & 31, wid = tid >> 5;
    const int wm = wid & 3, wn = wid >> 2;
    const uint32_t smb = smem_u32(smc);

    float4 af[4];
    uint4 bhf[2], blf[2];

    // ---- fetch / store helpers ----
    auto fetchAB = [&](int c) {
#pragma unroll
        for (int it = 0; it < 4; it++) {
            int idx = tid + it * 256;
            int r = idx >> 3, u = idx & 7;
            af[it] = *(const float4*)(A + (size_t)r * Din + c * BK + u * 4);
        }
#pragma unroll
        for (int it = 0; it < 2; it++) {
            int idx = tid + it * 256;
            int r = idx >> 4, u = idx & 15;
            bhf[it] = *(const uint4*)(Bh + (size_t)(c * BK + r) * Dout + u * 8);
            blf[it] = *(const uint4*)(Bl + (size_t)(c * BK + r) * Dout + u * 8);
        }
    };
    auto storeSm = [&](int s) {
#pragma unroll
        for (int it = 0; it < 4; it++) {
            int idx = tid + it * 256;
            int r = idx >> 3, u = idx & 7;
            float4 v = af[it];
            __nv_bfloat16 h0 = __float2bfloat16(v.x), h1 = __float2bfloat16(v.y);
            __nv_bfloat16 h2 = __float2bfloat16(v.z), h3 = __float2bfloat16(v.w);
            __nv_bfloat16 l0 = __float2bfloat16(v.x - __bfloat162float(h0));
            __nv_bfloat16 l1 = __float2bfloat16(v.y - __bfloat162float(h1));
            __nv_bfloat16 l2 = __float2bfloat16(v.z - __bfloat162float(h2));
            __nv_bfloat16 l3 = __float2bfloat16(v.w - __bfloat162float(h3));
            uint32_t off = (uint32_t)(r * ASTR + u * 4) * 2;
            *(uint2*)(smc + OFF_AH + s * A_STG + off) =
                make_uint2(pack_bf2(h0, h1), pack_bf2(h2, h3));
            *(uint2*)(smc + OFF_AL + s * A_STG + off) =
                make_uint2(pack_bf2(l0, l1), pack_bf2(l2, l3));
        }
#pragma unroll
        for (int it = 0; it < 2; it++) {
            int idx = tid + it * 256;
            int r = idx >> 4, u = idx & 15;
            uint32_t off = (uint32_t)(r * BSTR + u * 8) * 2;
            *(uint4*)(smc + OFF_BH + s * B_STG + off) = bhf[it];
            *(uint4*)(smc + OFF_BL + s * B_STG + off) = blf[it];
        }
    };
    auto compute = [&](int s) {
        const uint32_t aH = smb + OFF_AH + s * A_STG;
        const uint32_t aL = smb + OFF_AL + s * A_STG;
        const uint32_t bH = smb + OFF_BH + s * B_STG;
        const uint32_t bL = smb + OFF_BL + s * B_STG;
#pragma unroll
        for (int ks = 0; ks < 2; ks++) {
            uint32_t ah[2][4], al[2][4], bh[4][4], bl[4][4];
            const int arow = lane & 15;
            const int acol = ks * 16 + (lane >> 4) * 8;
#pragma unroll
            for (int mt = 0; mt < 2; mt++) {
                uint32_t off =
                    (uint32_t)((wm * 32 + mt * 16 + arow) * ASTR + acol) * 2;
                ldsm_x4(ah[mt], aH + off);
                ldsm_x4(al[mt], aL + off);
            }
            const int bk = ks * 16 + (lane & 15);
#pragma unroll
            for (int pr = 0; pr < 4; pr++) {
                uint32_t off = (uint32_t)(bk * BSTR + wn * 64 + pr * 16 +
                                          (lane >> 4) * 8) * 2;
                ldsm_x4_t(bh[pr], bH + off);
                ldsm_x4_t(bl[pr], bL + off);
            }
#pragma unroll
            for (int mt = 0; mt < 2; mt++)
#pragma unroll
                for (int nt = 0; nt < 8; nt++) {
                    const uint32_t* bhp = &bh[nt >> 1][(nt & 1) * 2];
                    const uint32_t* blp = &bl[nt >> 1][(nt & 1) * 2];
                    mma16816(acc[mt][nt], ah[mt], bhp);
                    mma16816(acc[mt][nt], ah[mt], blp);
                    mma16816(acc[mt][nt], al[mt], bhp);
                }
        }
    };

    // ---- pipelined mainloop ----
    fetchAB(0);
    storeSm(0);
    __syncthreads();
#pragma unroll 1
    for (int c = 0; c < Din / BK; c++) {
        if (c + 1 < Din / BK) fetchAB(c + 1);
        compute(c & 1);
        if (c + 1 < Din / BK) storeSm((c + 1) & 1);
        __syncthreads();
    }
}

// QKV GEMM: z selects weight + head-split fp32 destination
__global__ __launch_bounds__(256) void gemm_qkv_kernel(const float* __restrict__ x) {
    extern __shared__ char smc[];
    const int z = blockIdx.z;
    const int m0 = blockIdx.y * BM, n0 = blockIdx.x * BN;
    const __nv_bfloat16* Bh = g_wh + (size_t)z * Din * Dout + n0;
    const __nv_bfloat16* Bl = g_wl + (size_t)z * Din * Dout + n0;
    float* outp = (z == 0) ? g_q : (z == 1) ? g_k : g_v;

    float acc[2][8][4];
#pragma unroll
    for (int a = 0; a < 2; a++)
#pragma unroll
        for (int b = 0; b < 8; b++)
#pragma unroll
            for (int cc = 0; cc < 4; cc++) acc[a][b][cc] = 0.f;

    gemm_mainloop(x + (size_t)m0 * Din, Bh, Bl, smc, acc);

    const int lane = threadIdx.x & 31, wid = threadIdx.x >> 5;
    const int wm = wid & 3, wn = wid >> 2;
    const int h = (n0 >> 6) + wn;  // one head per warp column
#pragma unroll
    for (int mt = 0; mt < 2; mt++)
#pragma unroll
        for (int rr = 0; rr < 2; rr++) {
            int m = m0 + wm * 32 + mt * 16 + rr * 8 + (lane >> 2);
            int b = m >> 11, s = m & (Seq - 1);
            float* rowp = outp + (((size_t)b * NH + h) * Seq + s) * HD;
#pragma unroll
            for (int nt = 0; nt < 8; nt++) {
                float2 v = make_float2(acc[mt][nt][rr * 2 + 0],
                                       acc[mt][nt][rr * 2 + 1]);
                *(float2*)(rowp + nt * 8 + (lane & 3) * 2) = v;
            }
        }
}

// Out GEMM: ctx(fp32, inline hi/lo) @ Wo + bias -> d_out
__global__ __launch_bounds__(256) void gemm_out_kernel(const float* __restrict__ bias,
                                                       float* __restrict__ out) {
    extern __shared__ char smc[];
    const int m0 = blockIdx.y * BM, n0 = blockIdx.x * BN;
    const __nv_bfloat16* Bh = g_wh + (size_t)3 * Din * Dout + n0;
    const __nv_bfloat16* Bl = g_wl + (size_t)3 * Din * Dout + n0;

    float acc[2][8][4];
#pragma unroll
    for (int a = 0; a < 2; a++)
#pragma unroll
        for (int b = 0; b < 8; b++)
#pragma unroll
            for (int cc = 0; cc < 4; cc++) acc[a][b][cc] = 0.f;

    gemm_mainloop(g_ctx + (size_t)m0 * Dout, Bh, Bl, smc, acc);

    const int lane = threadIdx.x & 31, wid = threadIdx.x >> 5;
    const int wm = wid & 3, wn = wid >> 2;
#pragma unroll
    for (int mt = 0; mt < 2; mt++)
#pragma unroll
        for (int rr = 0; rr < 2; rr++) {
            int m = m0 + wm * 32 + mt * 16 + rr * 8 + (lane >> 2);
#pragma unroll
            for (int nt = 0; nt < 8; nt++) {
                int n = n0 + wn * 64 + nt * 8 + (lane & 3) * 2;
                float2 bb = *(const float2*)&bias[n];
                float2 v = make_float2(acc[mt][nt][rr * 2 + 0] + bb.x,
                                       acc[mt][nt][rr * 2 + 1] + bb.y);
                *(float2*)&out[(size_t)m * Dout + n] = v;
            }
        }
}

// ---------------------------------------------------------------------------
// Flash attention (fp32): 128-row q-tiles x 64-col k-tiles, 8x4 microtile
// ---------------------------------------------------------------------------
#define APIT 68
#define QS_OFF 0
#define KT_OFF (128 * APIT)
#define VS_OFF (KT_OFF + 64 * APIT)
#define PS_OFF (VS_OFF + 64 * APIT)
#define ATT_FLOATS (PS_OFF + 128 * APIT)
#define ATT_SMEM (ATT_FLOATS * 4)  // 104448 bytes

__global__ __launch_bounds__(256) void attn_kernel() {
    extern __shared__ float sm[];
    const int tid = threadIdx.x;
    const int tx = tid & 15;
    const int ty = tid >> 4;
    const int bx = blockIdx.x;
    const int h = blockIdx.y;
    const int bb = blockIdx.z;
    const int q0 = bx * 128;
    const size_t base = ((size_t)bb * NH + h) * Seq * HD;

    // Load Q tile (128 x 64)
#pragma unroll
    for (int i = 0; i < 8; i++) {
        int idx = tid + i * 256;
        int row = idx >> 4, u = idx & 15;
        float4 qv = *(const float4*)&g_q[base + (size_t)(q0 + row) * HD + u * 4];
        *(float4*)&sm[QS_OFF + row * APIT + u * 4] = qv;
    }

    float acc[8][4];
    float mrow[8], lrow[8];
#pragma unroll
    for (int i = 0; i < 8; i++) {
        mrow[i] = -1e30f;
        lrow[i] = 0.f;
#pragma unroll
        for (int j = 0; j < 4; j++) acc[i][j] = 0.f;
    }

    const int kt_max = 2 * bx + 2;
    for (int kt = 0; kt < kt_max; kt++) {
        const int k0 = kt * 64;
        __syncthreads();  // prev PV done (and Q visible first iter)

        // Load K transposed -> Kt[d][n], V natural -> Vs[n][d]
#pragma unroll
        for (int i = 0; i < 4; i++) {
            int idx = tid + i * 256;
            int n = idx >> 4, u = idx & 15;
            int d0 = u * 4;
            float4 kv = *(const float4*)&g_k[base + (size_t)(k0 + n) * HD + d0];
            sm[KT_OFF + (d0 + 0) * APIT + n] = kv.x;
            sm[KT_OFF + (d0 + 1) * APIT + n] = kv.y;
            sm[KT_OFF + (d0 + 2) * APIT + n] = kv.z;
            sm[KT_OFF + (d0 + 3) * APIT + n] = kv.w;
            float4 vv = *(const float4*)&g_v[base + (size_t)(k0 + n) * HD + d0];
            *(float4*)&sm[VS_OFF + n * APIT + d0] = vv;
        }
        __syncthreads();

        // S = Q @ K^T
        float s[8][4];
#pragma unroll
        for (int i = 0; i < 8; i++)
#pragma unroll
            for (int j = 0; j < 4; j++) s[i][j] = 0.f;

        for (int d4 = 0; d4 < 16; d4++) {
            float kt4[4][4];
#pragma unroll
            for (int dd = 0; dd < 4; dd++) {
                float4 t = *(const float4*)&sm[KT_OFF + (d4 * 4 + dd) * APIT + tx * 4];
                kt4[dd][0] = t.x; kt4[dd][1] = t.y; kt4[dd][2] = t.z; kt4[dd][3] = t.w;
            }
#pragma unroll
            for (int i = 0; i < 8; i++) {
                float4 q = *(const float4*)&sm[QS_OFF + (ty * 8 + i) * APIT + d4 * 4];
#pragma unroll
                for (int j = 0; j < 4; j++) {
                    s[i][j] = fmaf(q.x, kt4[0][j], s[i][j]);
                    s[i][j] = fmaf(q.y, kt4[1][j], s[i][j]);
                    s[i][j] = fmaf(q.z, kt4[2][j], s[i][j]);
                    s[i][j] = fmaf(q.w, kt4[3][j], s[i][j]);
                }
            }
        }

        // scale + causal mask
        const bool domask = (kt >= 2 * bx);
        const int coff = k0 - q0;
#pragma unroll
        for (int i = 0; i < 8; i++)
#pragma unroll
            for (int j = 0; j < 4; j++) {
                s[i][j] *= 0.125f;
                if (domask && (coff + tx * 4 + j) > (ty * 8 + i)) s[i][j] = -1e30f;
            }

        // online softmax
#pragma unroll
        for (int i = 0; i < 8; i++) {
            float mx = fmaxf(fmaxf(s[i][0], s[i][1]), fmaxf(s[i][2], s[i][3]));
#pragma unroll
            for (int off = 8; off >= 1; off >>= 1)
                mx = fmaxf(mx, __shfl_xor_sync(0xffffffffu, mx, off));
            float mn = fmaxf(mrow[i], mx);
            float alpha = __expf(mrow[i] - mn);
            mrow[i] = mn;
            float4 p;
            p.x = __expf(s[i][0] - mn);
            p.y = __expf(s[i][1] - mn);
            p.z = __expf(s[i][2] - mn);
            p.w = __expf(s[i][3] - mn);
            float rs = p.x + p.y + p.z + p.w;
#pragma unroll
            for (int off = 8; off >= 1; off >>= 1)
                rs += __shfl_xor_sync(0xffffffffu, rs, off);
            lrow[i] = lrow[i] * alpha + rs;
#pragma unroll
            for (int j = 0; j < 4; j++) acc[i][j] *= alpha;
            *(float4*)&sm[PS_OFF + (ty * 8 + i) * APIT + tx * 4] = p;
        }
        __syncwarp();  // P rows produced/consumed within one half-warp

        // acc += P @ V
        for (int c4 = 0; c4 < 16; c4++) {
            float v4[4][4];
#pragma unroll
            for (int cc = 0; cc < 4; cc++) {
                float4 t = *(const float4*)&sm[VS_OFF + (c4 * 4 + cc) * APIT + tx * 4];
                v4[cc][0] = t.x; v4[cc][1] = t.y; v4[cc][2] = t.z; v4[cc][3] = t.w;
            }
#pragma unroll
            for (int i = 0; i < 8; i++) {
                float4 p = *(const float4*)&sm[PS_OFF + (ty * 8 + i) * APIT + c4 * 4];
#pragma unroll
                for (int j = 0; j < 4; j++) {
                    acc[i][j] = fmaf(p.x, v4[0][j], acc[i][j]);
                    acc[i][j] = fmaf(p.y, v4[1][j], acc[i][j]);
                    acc[i][j] = fmaf(p.z, v4[2][j], acc[i][j]);
                    acc[i][j] = fmaf(p.w, v4[3][j], acc[i][j]);
                }
            }
        }
    }

    // Epilogue: ctx fp32
#pragma unroll
    for (int i = 0; i < 8; i++) {
        float inv = 1.f / lrow[i];
        int row = q0 + ty * 8 + i;
        float4 v = make_float4(acc[i][0] * inv, acc[i][1] * inv,
                               acc[i][2] * inv, acc[i][3] * inv);
        *(float4*)&g_ctx[((size_t)bb * Seq + row) * Dout + h * HD + tx * 4] = v;
    }
}

// ---------------------------------------------------------------------------
extern "C" void kernel_launch(void* const* d_in, const int* in_sizes, int n_in,
                              void* d_out, int out_size) {
    const float* x  = (const float*)d_in[0];
    const float* Wq = (const float*)d_in[1];
    const float* Wk = (const float*)d_in[2];
    const float* Wv = (const float*)d_in[3];
    const float* Wo = (const float*)d_in[4];
    const float* bo = (const float*)d_in[5];
    float* out = (float*)d_out;

    cudaFuncSetAttribute(gemm_qkv_kernel, cudaFuncAttributeMaxDynamicSharedMemorySize, GEMM_SMEM);
    cudaFuncSetAttribute(gemm_out_kernel, cudaFuncAttributeMaxDynamicSharedMemorySize, GEMM_SMEM);
    cudaFuncSetAttribute(attn_kernel, cudaFuncAttributeMaxDynamicSharedMemorySize, ATT_SMEM);

    wconv_kernel<<<dim3((Din * Dout / 4) / 256, 4), 256>>>(Wq, Wk, Wv, Wo);
    gemm_qkv_kernel<<<dim3(Dout / BN, Mrows / BM, 3), 256, GEMM_SMEM>>>(x);
    attn_kernel<<<dim3(Seq / 128, NH, Bsz), 256, ATT_SMEM>>>();
    gemm_out_kernel<<<dim3(Dout / BN, Mrows / BM), 256, GEMM_SMEM>>>(bo, out);
}